// round 14
// baseline (speedup 1.0000x reference)
#include <cuda_runtime.h>

// Problem constants
#define BB     1024
#define TT     2048
#define DD     5
#define HH     64
#define GG     256     // 4*H gates
#define OUTN   128
#define BTILE  7
#define THREADS 512
#define NCTA   147     // 147*7 = 1029 >= 1024 (last CTA: 2 valid, 5 dummy)

// Shared memory layout (bytes)
#define OFF_W1    0                 // ulonglong2[16 kp2][256 g] Whh0 paired   65536
#define OFF_WX    65536             // float [5][256]   Wih0 transposed        5120
#define OFF_HC    70656             // float2[64][8]    kp0-31: h1, kp32-63: h2 4096
#define OFF_PA    74752             // float[2 kh][2 chunks][1040] L1 partials 16640
#define OFF_PB    91392             // same for layer-2                       16640
#define OFF_XB    108032            // float [2][5][8]  x double buffer         320
#define SMEM_BYTES 108352

// partial-sum buffer strides (floats); chunk stride padded (1040 % 32 == 16)
#define P_CHUNK  1040
#define P_KH     2080

__device__ __forceinline__ unsigned long long ffma2(unsigned long long a,
                                                    unsigned long long b,
                                                    unsigned long long c) {
    unsigned long long d;
    asm("fma.rn.f32x2 %0, %1, %2, %3;" : "=l"(d) : "l"(a), "l"(b), "l"(c));
    return d;
}

__device__ __forceinline__ float sigf(float x) {
    return __fdividef(1.0f, 1.0f + __expf(-x));
}
__device__ __forceinline__ float tanh_fast(float x) {
    return __fdividef(2.0f, 1.0f + __expf(-2.0f * x)) - 1.0f;
}

__global__ void __launch_bounds__(THREADS)
lstm_fused_kernel(const float* __restrict__ x,
                  const float* __restrict__ Wih0, const float* __restrict__ Whh0,
                  const float* __restrict__ bih0, const float* __restrict__ bhh0,
                  const float* __restrict__ Wih1, const float* __restrict__ Whh1,
                  const float* __restrict__ bih1, const float* __restrict__ bhh1,
                  const float* __restrict__ Wfc,  const float* __restrict__ bfc,
                  float* __restrict__ out)
{
    extern __shared__ char smem[];
    float*  WX   = (float*) (smem + OFF_WX);
    float*  HCf  = (float*) (smem + OFF_HC);
    float*  PAf  = (float*) (smem + OFF_PA);
    float*  PBf  = (float*) (smem + OFF_PB);
    float*  XB   = (float*) (smem + OFF_XB);
    ulonglong2*       W1P  = (ulonglong2*)(smem + OFF_W1);
    const ulonglong2* HCu  = (const ulonglong2*)(smem + OFF_HC);
    const unsigned long long* HCl = (const unsigned long long*)(smem + OFF_HC);

    const int tid = threadIdx.x;
    const int g   = tid & 255;          // gate index
    const int kh  = tid >> 8;           // k-half (0 or 1)
    const int b0  = blockIdx.x * BTILE;
    const int kpbase = kh * 16;         // this thread's 16-kp slice (both layers)

    // ---- Layer-2 weights for this (gate, k-slice) -> 64 REGISTERS ----
    // w2r[0..15]  = Wih1 pairs for h1 kp [kpbase, kpbase+16)
    // w2r[16..31] = Whh1 pairs for h2 kp [kpbase, kpbase+16)  (HC slots 32+kp)
    unsigned long long w2r[32];
    {
        const unsigned long long* wi =
            (const unsigned long long*)(Wih1 + (size_t)g * HH);
        const unsigned long long* wh =
            (const unsigned long long*)(Whh1 + (size_t)g * HH);
        #pragma unroll
        for (int k = 0; k < 16; k++) w2r[k]      = wi[kpbase + k];
        #pragma unroll
        for (int k = 0; k < 16; k++) w2r[16 + k] = wh[kpbase + k];
    }

    // ---- Stage layer-1 weights into SMEM (kp-PAIRED for LDS.128) ----
    // W1P[kp2][g] = ( Whh0 pair for kp=2*kp2 , pair for kp=2*kp2+1 )
    for (int i = tid; i < GG * 16; i += THREADS) {
        int gg = i >> 4, kp2 = i & 15;
        const unsigned long long* srcu =
            (const unsigned long long*)(Whh0 + (size_t)gg * HH);
        ulonglong2 v;
        v.x = srcu[2 * kp2];
        v.y = srcu[2 * kp2 + 1];
        W1P[kp2 * GG + gg] = v;
    }
    for (int i = tid; i < GG * DD; i += THREADS) {
        int gg = i / DD, d = i - gg * DD;
        WX[d * GG + gg] = Wih0[i];
    }
    for (int i = tid; i < 64 * 8 * 2; i += THREADS) HCf[i] = 0.0f;   // h1,h2

    const float breg1 = bih0[g] + bhh0[g];
    const float breg2 = bih1[g] + bhh1[g];

    // initial x staging for iteration 0 (reads x(0))
    const int bb = tid / DD, dd = tid - (tid / DD) * DD;   // valid when tid<35
    if (tid < DD * BTILE) {
        int bidx = b0 + bb; if (bidx >= BB) bidx = BB - 1;
        XB[dd * 8 + bb] = x[((size_t)bidx * TT + 0) * DD + dd];
    }
    __syncthreads();

    // ---- updater mapping: all 512 threads -> unit uu in [0,64), batch ub in [0,8) ----
    const int uu  = tid >> 3;
    const int ub  = tid & 7;
    const bool upd = (ub < 7);
    const int hco1 = (uu >> 1) * 16 + ub * 2 + (uu & 1);     // h1 slot (floats)
    const int cb   = (ub >> 2) * P_CHUNK;                    // chunk offset
    const int bbm  = ub & 3;
    float c1 = 0.0f, c2 = 0.0f;

    // ===================== Pipelined recurrence, updaters hidden =====================
    // phase1(j): fused ACC (gates1(j) full -> PA, gates2(j-1) h1-part into accB)
    //            + L2-update: apply PB(j-1) -> h2(j-2)            [j >= 2]
    //            bar A
    // phase2(j): h2-only ACC (gates2(j-1) complete -> PB)
    //            + L1-update: apply PA(j) -> h1(j)
    //            bar B
    for (int j = 0; j <= TT + 1; ++j) {
        const int cur = j & 1, nxt = cur ^ 1;

        // prefetch x(j+1) into regs (hidden behind the ACC phase)
        float xpre = 0.0f;
        if (tid < DD * BTILE) {
            int tn = (j + 1 < TT) ? (j + 1) : (TT - 1);
            int bidx = b0 + bb; if (bidx >= BB) bidx = BB - 1;
            xpre = x[((size_t)bidx * TT + tn) * DD + dd];
        }

        // ================= PHASE 1 =================
        // accA init: bias + Wx.x(j) on kh0
        unsigned long long accA[BTILE];
        if (kh == 0) {
            float sx[BTILE];
            #pragma unroll
            for (int b = 0; b < BTILE; b++) sx[b] = breg1;
            const float* xrow = XB + cur * 40;
            #pragma unroll
            for (int d = 0; d < DD; d++) {
                float  w  = WX[d * GG + g];
                float4 xa = *(const float4*)(xrow + d * 8);
                float4 xc = *(const float4*)(xrow + d * 8 + 4);
                sx[0] += w * xa.x; sx[1] += w * xa.y; sx[2] += w * xa.z; sx[3] += w * xa.w;
                sx[4] += w * xc.x; sx[5] += w * xc.y; sx[6] += w * xc.z;
            }
            #pragma unroll
            for (int b = 0; b < BTILE; b++)
                accA[b] = (unsigned long long)__float_as_uint(sx[b]);
        } else {
            #pragma unroll
            for (int b = 0; b < BTILE; b++) accA[b] = 0ull;
        }

        unsigned long long accB[BTILE];
        if (kh == 0) {
            #pragma unroll
            for (int b = 0; b < BTILE; b++)
                accB[b] = (unsigned long long)__float_as_uint(breg2);
        } else {
            #pragma unroll
            for (int b = 0; b < BTILE; b++) accB[b] = 0ull;
        }

        // FUSED loop over h1 kp slice: paired weights (1 LDS.128 per 2 kp),
        // one h load stream, two FFMA streams.
        #pragma unroll
        for (int kk = 0; kk < 8; kk++) {
            const int kp2 = kh * 8 + kk;      // kp pair index
            ulonglong2 w12 = W1P[kp2 * GG + g];
            const int kp0 = 2 * kp2;
            {
                unsigned long long wA = w12.x;
                unsigned long long wB = w2r[2 * kk];
                ulonglong2 h01 = HCu[kp0 * 4 + 0];
                ulonglong2 h23 = HCu[kp0 * 4 + 1];
                ulonglong2 h45 = HCu[kp0 * 4 + 2];
                unsigned long long h6 = HCl[kp0 * 8 + 6];
                accA[0] = ffma2(wA, h01.x, accA[0]); accB[0] = ffma2(wB, h01.x, accB[0]);
                accA[1] = ffma2(wA, h01.y, accA[1]); accB[1] = ffma2(wB, h01.y, accB[1]);
                accA[2] = ffma2(wA, h23.x, accA[2]); accB[2] = ffma2(wB, h23.x, accB[2]);
                accA[3] = ffma2(wA, h23.y, accA[3]); accB[3] = ffma2(wB, h23.y, accB[3]);
                accA[4] = ffma2(wA, h45.x, accA[4]); accB[4] = ffma2(wB, h45.x, accB[4]);
                accA[5] = ffma2(wA, h45.y, accA[5]); accB[5] = ffma2(wB, h45.y, accB[5]);
                accA[6] = ffma2(wA, h6,    accA[6]); accB[6] = ffma2(wB, h6,    accB[6]);
            }
            {
                const int kp1 = kp0 + 1;
                unsigned long long wA = w12.y;
                unsigned long long wB = w2r[2 * kk + 1];
                ulonglong2 h01 = HCu[kp1 * 4 + 0];
                ulonglong2 h23 = HCu[kp1 * 4 + 1];
                ulonglong2 h45 = HCu[kp1 * 4 + 2];
                unsigned long long h6 = HCl[kp1 * 8 + 6];
                accA[0] = ffma2(wA, h01.x, accA[0]); accB[0] = ffma2(wB, h01.x, accB[0]);
                accA[1] = ffma2(wA, h01.y, accA[1]); accB[1] = ffma2(wB, h01.y, accB[1]);
                accA[2] = ffma2(wA, h23.x, accA[2]); accB[2] = ffma2(wB, h23.x, accB[2]);
                accA[3] = ffma2(wA, h23.y, accA[3]); accB[3] = ffma2(wB, h23.y, accB[3]);
                accA[4] = ffma2(wA, h45.x, accA[4]); accB[4] = ffma2(wB, h45.x, accB[4]);
                accA[5] = ffma2(wA, h45.y, accA[5]); accB[5] = ffma2(wB, h45.y, accB[5]);
                accA[6] = ffma2(wA, h6,    accA[6]); accB[6] = ffma2(wB, h6,    accB[6]);
            }
        }
        // publish layer-1 partials
        {
            float av[BTILE + 1];
            #pragma unroll
            for (int b = 0; b < BTILE; b++)
                av[b] = __uint_as_float((unsigned)accA[b]) +
                        __uint_as_float((unsigned)(accA[b] >> 32));
            av[7] = 0.0f;
            float* pbase = PAf + kh * P_KH + g * 4;
            *(float4*)(pbase)           = make_float4(av[0], av[1], av[2], av[3]);
            *(float4*)(pbase + P_CHUNK) = make_float4(av[4], av[5], av[6], av[7]);
        }
        if (tid < DD * BTILE) XB[nxt * 40 + dd * 8 + bb] = xpre;

        // ---- hidden L2-update: apply PB(j-1) -> h2(j-2) ----
        // PB written in phase2(j-1) (bar B between); fused loop above never
        // touches h2 or PB; h2 written here is read only after bar A.
        if (j >= 2 && upd) {
            const float* p0 = PBf + cb + bbm;
            const float* p1 = p0 + P_KH;
            float vi = p0[(uu)       * 4] + p1[(uu)       * 4];
            float vf = p0[(64  + uu) * 4] + p1[(64  + uu) * 4];
            float vg = p0[(128 + uu) * 4] + p1[(128 + uu) * 4];
            float vo = p0[(192 + uu) * 4] + p1[(192 + uu) * 4];
            float ai = sigf(vi), af = sigf(vf), ag = tanh_fast(vg), ao = sigf(vo);
            c2 = af * c2 + ai * ag;
            HCf[512 + hco1] = ao * tanh_fast(c2);
        }
        __syncthreads();   // bar A

        if (j == TT + 1) break;   // final h2 is now published; skip dead phase 2

        // ================= PHASE 2 =================
        // h2-only loop: accB += Whh1 . h2(j-2)   (h2 slots updated in phase 1)
        #pragma unroll
        for (int kk = 0; kk < 16; kk++) {
            const int kp = 32 + kpbase + kk;     // h2 region in HC
            unsigned long long wB = w2r[16 + kk];
            ulonglong2 h01 = HCu[kp * 4 + 0];
            ulonglong2 h23 = HCu[kp * 4 + 1];
            ulonglong2 h45 = HCu[kp * 4 + 2];
            unsigned long long h6 = HCl[kp * 8 + 6];
            accB[0] = ffma2(wB, h01.x, accB[0]); accB[1] = ffma2(wB, h01.y, accB[1]);
            accB[2] = ffma2(wB, h23.x, accB[2]); accB[3] = ffma2(wB, h23.y, accB[3]);
            accB[4] = ffma2(wB, h45.x, accB[4]); accB[5] = ffma2(wB, h45.y, accB[5]);
            accB[6] = ffma2(wB, h6,    accB[6]);
        }
        {
            float av[BTILE + 1];
            #pragma unroll
            for (int b = 0; b < BTILE; b++)
                av[b] = __uint_as_float((unsigned)accB[b]) +
                        __uint_as_float((unsigned)(accB[b] >> 32));
            av[7] = 0.0f;
            float* pbase = PBf + kh * P_KH + g * 4;
            *(float4*)(pbase)           = make_float4(av[0], av[1], av[2], av[3]);
            *(float4*)(pbase + P_CHUNK) = make_float4(av[4], av[5], av[6], av[7]);
        }

        // ---- hidden L1-update: apply PA(j) -> h1(j) ----
        // PA published before bar A; h1 written here is read after bar B.
        if (upd) {
            const float* p0 = PAf + cb + bbm;
            const float* p1 = p0 + P_KH;
            float vi = p0[(uu)       * 4] + p1[(uu)       * 4];
            float vf = p0[(64  + uu) * 4] + p1[(64  + uu) * 4];
            float vg = p0[(128 + uu) * 4] + p1[(128 + uu) * 4];
            float vo = p0[(192 + uu) * 4] + p1[(192 + uu) * 4];
            float ai = sigf(vi), af = sigf(vf), ag = tanh_fast(vg), ao = sigf(vo);
            c1 = af * c1 + ai * ag;
            HCf[hco1] = ao * tanh_fast(c1);
        }
        __syncthreads();   // bar B
    }

    // ========= Fused FC + ReLU: out[b][o] = relu(h2[b] . Wfc[o] + bfc[o]) =========
    // (bar A of the final iteration ordered the last h2 writes before this.)
    if (tid < 32 * BTILE) {
        const int b  = tid >> 5;
        const int o  = (tid & 31) * 4;
        const int bidx = b0 + b;
        if (bidx < BB) {
            const float* w0 = Wfc + (size_t)(o + 0) * HH;
            const float* w1 = Wfc + (size_t)(o + 1) * HH;
            const float* w2 = Wfc + (size_t)(o + 2) * HH;
            const float* w3 = Wfc + (size_t)(o + 3) * HH;
            float s0 = bfc[o], s1 = bfc[o + 1], s2 = bfc[o + 2], s3 = bfc[o + 3];
            #pragma unroll
            for (int u = 0; u < HH; u++) {
                float h = HCf[512 + (u >> 1) * 16 + b * 2 + (u & 1)];
                s0 += h * w0[u]; s1 += h * w1[u]; s2 += h * w2[u]; s3 += h * w3[u];
            }
            float4 r = make_float4(fmaxf(s0, 0.f), fmaxf(s1, 0.f),
                                   fmaxf(s2, 0.f), fmaxf(s3, 0.f));
            *(float4*)(out + (size_t)bidx * OUTN + o) = r;
        }
    }
}

extern "C" void kernel_launch(void* const* d_in, const int* in_sizes, int n_in,
                              void* d_out, int out_size)
{
    const float* x    = (const float*)d_in[0];
    const float* Wih0 = (const float*)d_in[1];
    const float* Whh0 = (const float*)d_in[2];
    const float* bih0 = (const float*)d_in[3];
    const float* bhh0 = (const float*)d_in[4];
    const float* Wih1 = (const float*)d_in[5];
    const float* Whh1 = (const float*)d_in[6];
    const float* bih1 = (const float*)d_in[7];
    const float* bhh1 = (const float*)d_in[8];
    const float* Wfc  = (const float*)d_in[9];
    const float* bfc  = (const float*)d_in[10];
    float* out = (float*)d_out;

    cudaFuncSetAttribute(lstm_fused_kernel,
                         cudaFuncAttributeMaxDynamicSharedMemorySize, SMEM_BYTES);

    lstm_fused_kernel<<<NCTA, THREADS, SMEM_BYTES>>>(
        x, Wih0, Whh0, bih0, bhh0, Wih1, Whh1, bih1, bhh1, Wfc, bfc, out);
}

// round 15
// speedup vs baseline: 1.1181x; 1.1181x over previous
#include <cuda_runtime.h>

// Problem constants
#define BB     1024
#define TT     2048
#define DD     5
#define HH     64
#define GG     256     // 4*H gates
#define OUTN   128
#define BTILE  7
#define THREADS 512
#define NCTA   147     // 147*7 = 1029 >= 1024 (last CTA: 2 valid, 5 dummy)

// Shared memory layout (bytes)
#define OFF_W1    0                 // float2[32][256]  Whh0 k-pairs          65536
#define OFF_WX    65536             // float [5][256]   Wih0 transposed        5120
#define OFF_HC    70656             // float2[64][8]    kp0-31: h1, kp32-63: h2 4096
#define OFF_PA    74752             // float[2 kh][2 chunks][1040] L1 partials 16640
#define OFF_PB    91392             // same for layer-2                       16640
#define OFF_XB    108032            // float [2][5][8]  x double buffer         320
#define SMEM_BYTES 108352

// partial-sum buffer strides (floats); chunk stride padded (1040 % 32 == 16)
#define P_CHUNK  1040
#define P_KH     2080

__device__ __forceinline__ unsigned long long ffma2(unsigned long long a,
                                                    unsigned long long b,
                                                    unsigned long long c) {
    unsigned long long d;
    asm("fma.rn.f32x2 %0, %1, %2, %3;" : "=l"(d) : "l"(a), "l"(b), "l"(c));
    return d;
}

__device__ __forceinline__ float sigf(float x) {
    return __fdividef(1.0f, 1.0f + __expf(-x));
}
__device__ __forceinline__ float tanh_fast(float x) {
    return __fdividef(2.0f, 1.0f + __expf(-2.0f * x)) - 1.0f;
}

__global__ void __launch_bounds__(THREADS)
lstm_fused_kernel(const float* __restrict__ x,
                  const float* __restrict__ Wih0, const float* __restrict__ Whh0,
                  const float* __restrict__ bih0, const float* __restrict__ bhh0,
                  const float* __restrict__ Wih1, const float* __restrict__ Whh1,
                  const float* __restrict__ bih1, const float* __restrict__ bhh1,
                  const float* __restrict__ Wfc,  const float* __restrict__ bfc,
                  float* __restrict__ out)
{
    extern __shared__ char smem[];
    float2* W1f = (float2*)(smem + OFF_W1);
    float*  WX  = (float*) (smem + OFF_WX);
    float*  HCf = (float*) (smem + OFF_HC);
    float*  PAf = (float*) (smem + OFF_PA);
    float*  PBf = (float*) (smem + OFF_PB);
    float*  XB  = (float*) (smem + OFF_XB);
    const unsigned long long* W1u = (const unsigned long long*)(smem + OFF_W1);
    const ulonglong2*         HCu = (const ulonglong2*)        (smem + OFF_HC);
    const unsigned long long* HCl = (const unsigned long long*)(smem + OFF_HC);

    const int tid = threadIdx.x;
    const int g   = tid & 255;          // gate index
    const int kh  = tid >> 8;           // k-half (0 or 1)
    const int b0  = blockIdx.x * BTILE;
    const int kpbase = kh * 16;         // this thread's 16-kp slice (both layers)

    // ---- Layer-2 weights for this (gate, k-slice) -> 64 REGISTERS ----
    unsigned long long w2r[32];
    {
        const unsigned long long* wi =
            (const unsigned long long*)(Wih1 + (size_t)g * HH);
        const unsigned long long* wh =
            (const unsigned long long*)(Whh1 + (size_t)g * HH);
        #pragma unroll
        for (int k = 0; k < 16; k++) w2r[k]      = wi[kpbase + k];
        #pragma unroll
        for (int k = 0; k < 16; k++) w2r[16 + k] = wh[kpbase + k];
    }

    // ---- Stage layer-1 weights into SMEM ----
    for (int i = tid; i < GG * (HH / 2); i += THREADS) {
        int gg = i >> 5, kp = i & 31;
        W1f[kp * GG + gg] = ((const float2*)Whh0)[i];
    }
    for (int i = tid; i < GG * DD; i += THREADS) {
        int gg = i / DD, d = i - gg * DD;
        WX[d * GG + gg] = Wih0[i];
    }
    for (int i = tid; i < 64 * 8 * 2; i += THREADS) HCf[i] = 0.0f;   // h1,h2

    const float breg1 = bih0[g] + bhh0[g];
    const float breg2 = bih1[g] + bhh1[g];

    // initial x staging for iteration 0 (reads x(0))
    const int bb = tid / DD, dd = tid - (tid / DD) * DD;   // valid when tid<35
    if (tid < DD * BTILE) {
        int bidx = b0 + bb; if (bidx >= BB) bidx = BB - 1;
        XB[dd * 8 + bb] = x[((size_t)bidx * TT + 0) * DD + dd];
    }
    __syncthreads();

    // ---- updater mapping: all 512 threads -> unit uu in [0,64), batch ub in [0,8) ----
    const int uu  = tid >> 3;
    const int ub  = tid & 7;
    const bool upd = (ub < 7);
    const int hco1 = (uu >> 1) * 16 + ub * 2 + (uu & 1);     // h1 slot (floats)
    const int cb   = (ub >> 2) * P_CHUNK;                    // chunk offset
    const int bbm  = ub & 3;
    float c1 = 0.0f, c2 = 0.0f;

    // ===================== Pipelined recurrence, updaters at phase TOPS =====================
    // interval (bar B(j-1) .. bar A(j)) = "phase 1 of j":
    //     L2-update: PB(j-1) -> h2(j-2)   [j >= 2]   (accA/accB not yet live)
    //     fused GEMV: gates1(j) -> PA ; gates2(j-1) h1-part -> accB
    // interval (bar A(j) .. bar B(j)) = "phase 2 of j":
    //     L1-update: PA(j) -> h1(j)                   (only accB live)
    //     h2-only GEMV: gates2(j-1) complete -> PB
    for (int j = 0; j <= TT + 1; ++j) {
        const int cur = j & 1, nxt = cur ^ 1;

        // ---- L2-update at phase-1 top: apply PB(j-1) -> h2(j-2) ----
        // PB(j-1) published before bar B(j-1); h2 written here is read only
        // after bar A (phase-2 GEMV); h2 slots disjoint from h1 reads below.
        if (j >= 2 && upd) {
            const float* p0 = PBf + cb + bbm;
            const float* p1 = p0 + P_KH;
            float vi = p0[(uu)       * 4] + p1[(uu)       * 4];
            float vf = p0[(64  + uu) * 4] + p1[(64  + uu) * 4];
            float vg = p0[(128 + uu) * 4] + p1[(128 + uu) * 4];
            float vo = p0[(192 + uu) * 4] + p1[(192 + uu) * 4];
            float ai = sigf(vi), af = sigf(vf), ag = tanh_fast(vg), ao = sigf(vo);
            c2 = af * c2 + ai * ag;
            HCf[512 + hco1] = ao * tanh_fast(c2);
        }
        if (j == TT + 1) break;   // final h2(TT-1) just written

        // prefetch x(j+1) into regs (hidden behind the ACC phase)
        float xpre = 0.0f;
        if (tid < DD * BTILE) {
            int tn = (j + 1 < TT) ? (j + 1) : (TT - 1);
            int bidx = b0 + bb; if (bidx >= BB) bidx = BB - 1;
            xpre = x[((size_t)bidx * TT + tn) * DD + dd];
        }

        // ---------- accA init: bias + Wx.x(j) on kh0 ----------
        unsigned long long accA[BTILE];
        if (kh == 0) {
            float sx[BTILE];
            #pragma unroll
            for (int b = 0; b < BTILE; b++) sx[b] = breg1;
            const float* xrow = XB + cur * 40;
            #pragma unroll
            for (int d = 0; d < DD; d++) {
                float  w  = WX[d * GG + g];
                float4 xa = *(const float4*)(xrow + d * 8);
                float4 xc = *(const float4*)(xrow + d * 8 + 4);
                sx[0] += w * xa.x; sx[1] += w * xa.y; sx[2] += w * xa.z; sx[3] += w * xa.w;
                sx[4] += w * xc.x; sx[5] += w * xc.y; sx[6] += w * xc.z;
            }
            #pragma unroll
            for (int b = 0; b < BTILE; b++)
                accA[b] = (unsigned long long)__float_as_uint(sx[b]);
        } else {
            #pragma unroll
            for (int b = 0; b < BTILE; b++) accA[b] = 0ull;
        }

        unsigned long long accB[BTILE];
        if (kh == 0) {
            #pragma unroll
            for (int b = 0; b < BTILE; b++)
                accB[b] = (unsigned long long)__float_as_uint(breg2);
        } else {
            #pragma unroll
            for (int b = 0; b < BTILE; b++) accB[b] = 0ull;
        }

        // ---------- FUSED loop over h1 kp slice: one h load, two FFMA streams ----------
        #pragma unroll
        for (int kk = 0; kk < 16; kk++) {
            const int kp = kpbase + kk;
            unsigned long long wA = W1u[kp * GG + g];
            unsigned long long wB = w2r[kk];
            ulonglong2 h01 = HCu[kp * 4 + 0];
            ulonglong2 h23 = HCu[kp * 4 + 1];
            ulonglong2 h45 = HCu[kp * 4 + 2];
            unsigned long long h6 = HCl[kp * 8 + 6];
            accA[0] = ffma2(wA, h01.x, accA[0]); accB[0] = ffma2(wB, h01.x, accB[0]);
            accA[1] = ffma2(wA, h01.y, accA[1]); accB[1] = ffma2(wB, h01.y, accB[1]);
            accA[2] = ffma2(wA, h23.x, accA[2]); accB[2] = ffma2(wB, h23.x, accB[2]);
            accA[3] = ffma2(wA, h23.y, accA[3]); accB[3] = ffma2(wB, h23.y, accB[3]);
            accA[4] = ffma2(wA, h45.x, accA[4]); accB[4] = ffma2(wB, h45.x, accB[4]);
            accA[5] = ffma2(wA, h45.y, accA[5]); accB[5] = ffma2(wB, h45.y, accB[5]);
            accA[6] = ffma2(wA, h6,    accA[6]); accB[6] = ffma2(wB, h6,    accB[6]);
        }
        // publish layer-1 partials (accA dead afterwards)
        {
            float av[BTILE + 1];
            #pragma unroll
            for (int b = 0; b < BTILE; b++)
                av[b] = __uint_as_float((unsigned)accA[b]) +
                        __uint_as_float((unsigned)(accA[b] >> 32));
            av[7] = 0.0f;
            float* pbase = PAf + kh * P_KH + g * 4;
            *(float4*)(pbase)           = make_float4(av[0], av[1], av[2], av[3]);
            *(float4*)(pbase + P_CHUNK) = make_float4(av[4], av[5], av[6], av[7]);
        }
        if (tid < DD * BTILE) XB[nxt * 40 + dd * 8 + bb] = xpre;
        __syncthreads();   // bar A: PA/XB published; h1/PB reads complete

        // ---- L1-update at phase-2 top: apply PA(j) -> h1(j) ----
        // PA published before bar A; h1 written here is read after bar B;
        // h1 slots disjoint from the h2 reads of the GEMV below.
        if (upd) {
            const float* p0 = PAf + cb + bbm;
            const float* p1 = p0 + P_KH;
            float vi = p0[(uu)       * 4] + p1[(uu)       * 4];
            float vf = p0[(64  + uu) * 4] + p1[(64  + uu) * 4];
            float vg = p0[(128 + uu) * 4] + p1[(128 + uu) * 4];
            float vo = p0[(192 + uu) * 4] + p1[(192 + uu) * 4];
            float ai = sigf(vi), af = sigf(vf), ag = tanh_fast(vg), ao = sigf(vo);
            c1 = af * c1 + ai * ag;
            HCf[hco1] = ao * tanh_fast(c1);
        }

        // ---------- h2-only loop: accB += Whh1 . h2(j-2) ----------
        #pragma unroll
        for (int kk = 0; kk < 16; kk++) {
            const int kp = 32 + kpbase + kk;     // h2 region in HC
            unsigned long long wB = w2r[16 + kk];
            ulonglong2 h01 = HCu[kp * 4 + 0];
            ulonglong2 h23 = HCu[kp * 4 + 1];
            ulonglong2 h45 = HCu[kp * 4 + 2];
            unsigned long long h6 = HCl[kp * 8 + 6];
            accB[0] = ffma2(wB, h01.x, accB[0]); accB[1] = ffma2(wB, h01.y, accB[1]);
            accB[2] = ffma2(wB, h23.x, accB[2]); accB[3] = ffma2(wB, h23.y, accB[3]);
            accB[4] = ffma2(wB, h45.x, accB[4]); accB[5] = ffma2(wB, h45.y, accB[5]);
            accB[6] = ffma2(wB, h6,    accB[6]);
        }
        {
            float av[BTILE + 1];
            #pragma unroll
            for (int b = 0; b < BTILE; b++)
                av[b] = __uint_as_float((unsigned)accB[b]) +
                        __uint_as_float((unsigned)(accB[b] >> 32));
            av[7] = 0.0f;
            float* pbase = PBf + kh * P_KH + g * 4;
            *(float4*)(pbase)           = make_float4(av[0], av[1], av[2], av[3]);
            *(float4*)(pbase + P_CHUNK) = make_float4(av[4], av[5], av[6], av[7]);
        }
        __syncthreads();   // bar B: PB/h1 published for next iteration
    }
    __syncthreads();   // order final h2 writes before FC reads

    // ========= Fused FC + ReLU: out[b][o] = relu(h2[b] . Wfc[o] + bfc[o]) =========
    if (tid < 32 * BTILE) {
        const int b  = tid >> 5;
        const int o  = (tid & 31) * 4;
        const int bidx = b0 + b;
        if (bidx < BB) {
            const float* w0 = Wfc + (size_t)(o + 0) * HH;
            const float* w1 = Wfc + (size_t)(o + 1) * HH;
            const float* w2 = Wfc + (size_t)(o + 2) * HH;
            const float* w3 = Wfc + (size_t)(o + 3) * HH;
            float s0 = bfc[o], s1 = bfc[o + 1], s2 = bfc[o + 2], s3 = bfc[o + 3];
            #pragma unroll
            for (int u = 0; u < HH; u++) {
                float h = HCf[512 + (u >> 1) * 16 + b * 2 + (u & 1)];
                s0 += h * w0[u]; s1 += h * w1[u]; s2 += h * w2[u]; s3 += h * w3[u];
            }
            float4 r = make_float4(fmaxf(s0, 0.f), fmaxf(s1, 0.f),
                                   fmaxf(s2, 0.f), fmaxf(s3, 0.f));
            *(float4*)(out + (size_t)bidx * OUTN + o) = r;
        }
    }
}

extern "C" void kernel_launch(void* const* d_in, const int* in_sizes, int n_in,
                              void* d_out, int out_size)
{
    const float* x    = (const float*)d_in[0];
    const float* Wih0 = (const float*)d_in[1];
    const float* Whh0 = (const float*)d_in[2];
    const float* bih0 = (const float*)d_in[3];
    const float* bhh0 = (const float*)d_in[4];
    const float* Wih1 = (const float*)d_in[5];
    const float* Whh1 = (const float*)d_in[6];
    const float* bih1 = (const float*)d_in[7];
    const float* bhh1 = (const float*)d_in[8];
    const float* Wfc  = (const float*)d_in[9];
    const float* bfc  = (const float*)d_in[10];
    float* out = (float*)d_out;

    cudaFuncSetAttribute(lstm_fused_kernel,
                         cudaFuncAttributeMaxDynamicSharedMemorySize, SMEM_BYTES);

    lstm_fused_kernel<<<NCTA, THREADS, SMEM_BYTES>>>(
        x, Wih0, Whh0, bih0, bhh0, Wih1, Whh1, bih1, bhh1, Wfc, bfc, out);
}